// round 12
// baseline (speedup 1.0000x reference)
#include <cuda_runtime.h>

#define Bsz 512
#define Tt  128
#define Ff  256
#define Hh  384
#define Ll  3
#define Kw  10
#define LAB 25
#define GATES 1542   // 4*H + 2*L
#define NHT 32       // n-tiles (each 12 hcols x 4 gates = 48 gate cols)
#define HT  12
#define NTW 48
#define BKF 48       // A k-block
#define NKB 8        // 384 / 48
#define NCTA 128     // persistent grid (32 n-tiles x 4 b-tiles)

// ---------------- device scratch ----------------
__device__ __align__(16) float g_xw[(size_t)Bsz * Tt * GATES];    // [b*T+t][n]
__device__ __align__(16) float g_xwT[(size_t)Tt * GATES * Bsz];   // [t][n][b]
__device__ __align__(16) float g_hT[2][Hh][Bsz];                  // parity h, transposed
__device__ __align__(16) float g_cT[Hh][Bsz];
__device__ __align__(16) float g_hhistT[(size_t)Tt * Hh * Bsz];   // [t][h][b]
__device__ __align__(16) float g_dist[Tt * Bsz];
__device__ __align__(16) float g_p6s[3][Bsz][8];                  // 3-phase h@rw[:,0:6] sums
__device__ __align__(16) float g_Brep[NHT][Hh][NTW];              // repacked rec_w gate cols
__device__ unsigned g_bar_cnt;                                    // grid barrier state
__device__ unsigned g_bar_gen;

typedef unsigned long long ull;
__device__ __forceinline__ ull splat2(float x) {
    ull r; asm("mov.b64 %0, {%1, %1};" : "=l"(r) : "f"(x)); return r;
}
__device__ __forceinline__ void fma2(ull& d, ull a, ull b) {
    asm("fma.rn.f32x2 %0, %1, %2, %3;" : "=l"(d) : "l"(a), "l"(b), "l"(d));
}
__device__ __forceinline__ float2 unpk(ull v) {
    float2 r; asm("mov.b64 {%0, %1}, %2;" : "=f"(r.x), "=f"(r.y) : "l"(v)); return r;
}
__device__ __forceinline__ float sigf(float x) { return 1.0f / (1.0f + __expf(-x)); }
__device__ __forceinline__ float tanhfast(float x) { return 1.0f - 2.0f / (1.0f + __expf(2.0f * x)); }

// Software grid barrier: all NCTA CTAs resident (1/SM, single wave) -> no deadlock.
__device__ __forceinline__ void grid_barrier() {
    __syncthreads();
    if (threadIdx.x == 0) {
        unsigned gen;
        asm volatile("ld.global.acquire.gpu.u32 %0, [%1];" : "=r"(gen)
                     : "l"(&g_bar_gen) : "memory");
        __threadfence();                      // release prior writes
        unsigned prev = atomicAdd(&g_bar_cnt, 1);
        if (prev == NCTA - 1) {
            atomicExch(&g_bar_cnt, 0);
            __threadfence();
            atomicExch(&g_bar_gen, gen + 1);  // open the gate
        } else {
            unsigned cur;
            do {
                __nanosleep(64);
                asm volatile("ld.global.acquire.gpu.u32 %0, [%1];" : "=r"(cur)
                             : "l"(&g_bar_gen) : "memory");
            } while (cur == gen);
        }
    }
    __syncthreads();
}

// ---------------- init ----------------
__global__ void init_state() {
    int stride = gridDim.x * blockDim.x;
    int tid0 = blockIdx.x * blockDim.x + threadIdx.x;
    float* h = &g_hT[0][0][0];
    for (int i = tid0; i < 2 * Hh * Bsz; i += stride) h[i] = 0.0f;
    float* c = &g_cT[0][0];
    for (int i = tid0; i < Hh * Bsz; i += stride) c[i] = 0.0f;
    float* p = &g_p6s[0][0][0];
    for (int i = tid0; i < 3 * Bsz * 8; i += stride) p[i] = 0.0f;
    if (tid0 == 0) { g_bar_cnt = 0; }
}

// ---------------- prep_B: repack rec_w gate cols into [ht][k][hc*4+j] ----------------
__global__ void prep_B(const float* __restrict__ rw) {
    int idx = blockIdx.x * blockDim.x + threadIdx.x;
    if (idx >= NHT * Hh * NTW) return;
    int ht = idx / (Hh * NTW);
    int rem = idx % (Hh * NTW);
    int k = rem / NTW, c = rem % NTW;
    int hc = c >> 2, j = c & 3;
    (&g_Brep[0][0][0])[idx] = rw[(size_t)k * GATES + 6 + j * Hh + ht * HT + hc];
}

// ============ gemm_xw: g_xw = [X, t>0] @ kernel_w + kernel_b + rec_b (+t-rows) =====
__global__ __launch_bounds__(256, 2) void gemm_xw(const float* __restrict__ X,
                                                  const float* __restrict__ kw,
                                                  const float* __restrict__ kbias,
                                                  const float* __restrict__ rw,
                                                  const float* __restrict__ rbias) {
    __shared__ __align__(16) float As[2][16][128];
    __shared__ __align__(16) float Bs[2][16][128];
    const int bn = blockIdx.x * 128, bm = blockIdx.y * 128;
    const int tid = threadIdx.x;
    const int tm = (tid >> 4) << 3, tn = (tid & 15) << 3;
    const int a_r = tid >> 2, a_k4 = (tid & 3) * 4;
    const int b_k = tid >> 6, b_n = (tid & 63) * 2;

    float4 pa[2]; float2 pb[4];
    ull acc2[4][8] = {};

    auto ldA = [&](int k0) {
#pragma unroll
        for (int r = 0; r < 2; r++)
            pa[r] = *(const float4*)(X + (size_t)(bm + a_r + 64 * r) * Ff + k0 + a_k4);
    };
    auto ldB = [&](int k0) {
#pragma unroll
        for (int r = 0; r < 4; r++) {
            int n = bn + b_n;
            float2 v = make_float2(0.0f, 0.0f);
            if (n < GATES) v = *(const float2*)(kw + (size_t)(k0 + b_k + 4 * r) * GATES + n);
            pb[r] = v;
        }
    };
    auto stA = [&](int buf) {
#pragma unroll
        for (int r = 0; r < 2; r++) {
            As[buf][a_k4 + 0][a_r + 64 * r] = pa[r].x;
            As[buf][a_k4 + 1][a_r + 64 * r] = pa[r].y;
            As[buf][a_k4 + 2][a_r + 64 * r] = pa[r].z;
            As[buf][a_k4 + 3][a_r + 64 * r] = pa[r].w;
        }
    };
    auto stB = [&](int buf) {
#pragma unroll
        for (int r = 0; r < 4; r++) {
            Bs[buf][b_k + 4 * r][b_n] = pb[r].x;
            Bs[buf][b_k + 4 * r][b_n + 1] = pb[r].y;
        }
    };

    const int NB = Ff / 16;
    ldA(0); ldB(0); stA(0); stB(0);
    __syncthreads();
    for (int kblk = 0; kblk < NB; kblk++) {
        int nxt = kblk + 1;
        if (nxt < NB) { ldA(nxt * 16); ldB(nxt * 16); }
        int p = kblk & 1;
#pragma unroll
        for (int kk = 0; kk < 16; kk++) {
            ulonglong2 a01 = *(const ulonglong2*)&As[p][kk][tm];
            ulonglong2 a23 = *(const ulonglong2*)&As[p][kk][tm + 4];
            float4 b0 = *(const float4*)&Bs[p][kk][tn];
            float4 b1 = *(const float4*)&Bs[p][kk][tn + 4];
            ull ar[4] = {a01.x, a01.y, a23.x, a23.y};
            ull bs[8] = {splat2(b0.x), splat2(b0.y), splat2(b0.z), splat2(b0.w),
                         splat2(b1.x), splat2(b1.y), splat2(b1.z), splat2(b1.w)};
#pragma unroll
            for (int ip = 0; ip < 4; ip++)
#pragma unroll
                for (int j = 0; j < 8; j++) fma2(acc2[ip][j], ar[ip], bs[j]);
        }
        if (nxt < NB) { int q = nxt & 1; stA(q); stB(q); }
        __syncthreads();
    }
#pragma unroll
    for (int j = 0; j < 8; j++) {
        int n = bn + tn + j;
        if (n >= GATES) continue;
        float base = kbias[n] + rbias[n];
        float tadd = kw[(size_t)Ff * GATES + n] + rw[(size_t)Hh * GATES + n];
#pragma unroll
        for (int ip = 0; ip < 4; ip++) {
            int m0 = bm + tm + ip * 2;
            float2 v = unpk(acc2[ip][j]);
            int t0 = m0 & (Tt - 1), t1 = (m0 + 1) & (Tt - 1);
            g_xw[(size_t)m0 * GATES + n]       = v.x + base + (t0 > 0 ? tadd : 0.0f);
            g_xw[(size_t)(m0 + 1) * GATES + n] = v.y + base + (t1 > 0 ? tadd : 0.0f);
        }
    }
}

// ---------------- transpose_xw: g_xw[b*T+t][n] -> g_xwT[t][n][b] ----------------
__global__ __launch_bounds__(256) void transpose_xw() {
    __shared__ float tile[32][33];
    const int n0 = blockIdx.x * 32, b0 = blockIdx.y * 32, t = blockIdx.z;
    const int tx = threadIdx.x & 31, ty = threadIdx.x >> 5;
#pragma unroll
    for (int i = 0; i < 4; i++) {
        int b = b0 + ty + i * 8;
        int n = n0 + tx;
        float v = 0.0f;
        if (n < GATES) v = g_xw[((size_t)b * Tt + t) * GATES + n];
        tile[ty + i * 8][tx] = v;
    }
    __syncthreads();
#pragma unroll
    for (int i = 0; i < 4; i++) {
        int n = n0 + ty + i * 8;
        if (n < GATES)
            g_xwT[((size_t)t * GATES + n) * Bsz + b0 + tx] = tile[tx][ty + i * 8];
    }
}

// ============ recurrence: PERSISTENT kernel — all 128 steps in one launch ============
// 128 CTAs (ht = cta&31 n-tile, bt = cta>>5 b-tile), 384 threads (12 warps, 3/SMSP).
// B tile + rw6 loaded ONCE; per step: xs load + GEMM + update + one grid barrier.
__global__ __launch_bounds__(384, 1) void recurrence(const float* __restrict__ rw) {
    extern __shared__ float sm[];
    float* Bs  = sm;                    // [384][52]      19968
    float* As  = Bs + 384 * 52;         // [2][48][128]   12288
    float* xs  = As + 2 * 48 * 128;     // [48][128]       6144
    float* p6p = xs + 48 * 128;         // [12][130][6]    9360
    float* fis = p6p + 12 * 130 * 6;    // [128][6]         768
    float* rw6 = fis + 128 * 6;         // [12][6]           72

    const int tid = threadIdx.x;
    const int ht = blockIdx.x & (NHT - 1);
    const int bm = (blockIdx.x >> 5) * 128;
    const int trow = tid & 15, tcol = tid >> 4;

    // ---- one-time: resident B tile + rw6 ----
    {
        const float4* src = (const float4*)&g_Brep[ht][0][0];   // 4608 float4
#pragma unroll
        for (int r = 0; r < 12; r++) {
            int idx = tid + 384 * r;
            float4 v = src[idx];
            int k = idx / 12, c4 = idx % 12;
            *(float4*)&Bs[k * 52 + c4 * 4] = v;
        }
    }
    if (tid < HT * 6)
        rw6[tid] = rw[(size_t)(ht * HT + tid / 6) * GATES + (tid % 6)];

    const float* hsrc;
    float4 pa[4];
    auto ldA = [&](int blk) {
#pragma unroll
        for (int r = 0; r < 4; r++) {
            int idx = tid + 384 * r;
            int kr = idx >> 5, bq = idx & 31;
            pa[r] = *(const float4*)(hsrc + (size_t)(blk * BKF + kr) * Bsz + bm + bq * 4);
        }
    };
    auto stA = [&](int buf) {
#pragma unroll
        for (int r = 0; r < 4; r++) {
            int idx = tid + 384 * r;
            int kr = idx >> 5, bq = idx & 31;
            *(float4*)&As[(buf * 48 + kr) * 128 + bq * 4] = pa[r];
        }
    };

    for (int t = 0; t < Tt; t++) {
        const int rd = t & 1, wr = rd ^ 1;
        hsrc = &g_hT[rd][0][0];

        // ---- phase A: xs tile + first A block + softmax6 ----
#pragma unroll
        for (int r = 0; r < 4; r++) {       // xw tile [c][b], 1536 float4
            int idx = tid + 384 * r;
            int c = idx >> 5, bq = idx & 31;
            int hc = c >> 2, j = c & 3;
            const float4* src = (const float4*)(g_xwT
                + ((size_t)t * GATES + 6 + j * Hh + ht * HT + hc) * Bsz + bm);
            *(float4*)&xs[c * 128 + bq * 4] = src[bq];
        }
        ldA(0); stA(0);

        if (tid < 128) {   // softmax: xw cols 0..5 + prev-step p6 (3-phase buffer)
            int b = bm + tid;
            const float* pp = &g_p6s[t % 3][b][0];
            float a0 = g_xwT[((size_t)t * GATES + 0) * Bsz + b] + pp[0];
            float a1 = g_xwT[((size_t)t * GATES + 1) * Bsz + b] + pp[1];
            float a2 = g_xwT[((size_t)t * GATES + 2) * Bsz + b] + pp[2];
            float a3 = g_xwT[((size_t)t * GATES + 3) * Bsz + b] + pp[3];
            float a4 = g_xwT[((size_t)t * GATES + 4) * Bsz + b] + pp[4];
            float a5 = g_xwT[((size_t)t * GATES + 5) * Bsz + b] + pp[5];
            float m1 = fmaxf(a0, fmaxf(a1, a2));
            float e0 = __expf(a0 - m1), e1 = __expf(a1 - m1), e2 = __expf(a2 - m1);
            float inv = 1.0f / (e0 + e1 + e2);
            float f0 = e0 * inv, f1 = (e0 + e1) * inv, f2 = (e0 + e1 + e2) * inv;
            float m2 = fmaxf(a3, fmaxf(a4, a5));
            float q0 = __expf(a3 - m2), q1 = __expf(a4 - m2), q2 = __expf(a5 - m2);
            float inv2 = 1.0f / (q0 + q1 + q2);
            fis[tid * 6 + 0] = f0; fis[tid * 6 + 1] = f1; fis[tid * 6 + 2] = f2;
            fis[tid * 6 + 3] = (q0 + q1 + q2) * inv2;
            fis[tid * 6 + 4] = (q1 + q2) * inv2;
            fis[tid * 6 + 5] = q2 * inv2;
            if (ht == 0) {
                g_dist[t * Bsz + b] = 1.0f - (f0 + f1 + f2) * (1.0f / 3.0f);
                float4 z = make_float4(0.0f, 0.0f, 0.0f, 0.0f);
                *(float4*)&g_p6s[(t + 2) % 3][b][0] = z;   // zero buffer step t+1 adds into
                *(float4*)&g_p6s[(t + 2) % 3][b][4] = z;
            }
        }
        __syncthreads();

        // ---- GEMM: 8 k-blocks; B resident, A double-buffered, register prefetch ----
        ull acc[4][2] = {};
        for (int blk = 0; blk < NKB; blk++) {
            if (blk < NKB - 1) ldA(blk + 1);
            const float* Ab = &As[(blk & 1) * 48 * 128];
            const float* Bb = &Bs[blk * BKF * 52];
            ulonglong2 a0 = *(const ulonglong2*)&Ab[4 * trow];
            ulonglong2 a1 = *(const ulonglong2*)&Ab[4 * trow + 64];
            float2 b2 = *(const float2*)&Bb[2 * tcol];
#pragma unroll
            for (int kk = 0; kk < BKF; kk++) {
                ulonglong2 na0, na1; float2 nb2;
                if (kk < BKF - 1) {
                    na0 = *(const ulonglong2*)&Ab[(kk + 1) * 128 + 4 * trow];
                    na1 = *(const ulonglong2*)&Ab[(kk + 1) * 128 + 4 * trow + 64];
                    nb2 = *(const float2*)&Bb[(kk + 1) * 52 + 2 * tcol];
                }
                ull b0 = splat2(b2.x), b1 = splat2(b2.y);
                fma2(acc[0][0], a0.x, b0); fma2(acc[0][1], a0.x, b1);
                fma2(acc[1][0], a0.y, b0); fma2(acc[1][1], a0.y, b1);
                fma2(acc[2][0], a1.x, b0); fma2(acc[2][1], a1.x, b1);
                fma2(acc[3][0], a1.y, b0); fma2(acc[3][1], a1.y, b1);
                if (kk < BKF - 1) { a0 = na0; a1 = na1; b2 = nb2; }
            }
            if (blk < NKB - 1) stA((blk + 1) & 1);
            __syncthreads();
        }

        // ---- add GEMM result into xw tile (xs) ----
#pragma unroll
        for (int p = 0; p < 4; p++) {
            int r0 = 4 * trow + (p & 1) * 2 + (p >> 1) * 64;
#pragma unroll
            for (int j = 0; j < 2; j++) {
                int c = 2 * tcol + j;
                float2 x = *(float2*)&xs[c * 128 + r0];
                float2 v = unpk(acc[p][j]);
                x.x += v.x; x.y += v.y;
                *(float2*)&xs[c * 128 + r0] = x;
            }
        }
        __syncthreads();

        // ---- per (b, hcol) gate nonlinearity + state update ----
#pragma unroll
        for (int r = 0; r < 4; r++) {
            int idx = tid + 384 * r;          // 1536 = 128 b x 12 hc
            int b = idx & 127, hc = idx >> 7;
            int h_g = ht * HT + hc;
            int l = h_g >> 7;
            float fg = sigf(xs[(hc * 4 + 0) * 128 + b]);
            float ig = sigf(xs[(hc * 4 + 1) * 128 + b]);
            float og = sigf(xs[(hc * 4 + 2) * 128 + b]);
            float ci = tanhfast(xs[(hc * 4 + 3) * 128 + b]);
            float F = fis[b * 6 + l], I = fis[b * 6 + 3 + l];
            int bg = bm + b;
            float cold = g_cT[h_g][bg];
            float ov = F * I;
            float cn = ov * (fg * cold + ig * ci) + (F - ov) * cold + (I - ov) * ci;
            g_cT[h_g][bg] = cn;
            float hn = og * tanhfast(cn);
            g_hT[wr][h_g][bg] = hn;
            g_hhistT[((size_t)t * Hh + h_g) * Bsz + bg] = hn;
#pragma unroll
            for (int c = 0; c < 6; c++)
                p6p[hc * 780 + b * 6 + c] = hn * rw6[hc * 6 + c];
        }
        __syncthreads();

        // ---- reduce p6 over hcols into next step's buffer ----
#pragma unroll
        for (int r = 0; r < 2; r++) {
            int idx = tid + 384 * r;          // 768 = 128 b x 6 c
            int b = idx / 6, c = idx % 6;
            float s = 0.0f;
#pragma unroll
            for (int hc = 0; hc < HT; hc++) s += p6p[hc * 780 + b * 6 + c];
            atomicAdd(&g_p6s[(t + 1) % 3][bm + b][c], s);
        }

        grid_barrier();   // publish h[wr], p6, dist to all CTAs for step t+1
    }
}

// ---------------- finalize: per-batch theme/conv/out at t = v_len-1 ----------------
#define GROUP 4
#define FIN_SMEM_FLOATS (GROUP * 3840 + GROUP * Hh + GROUP * Hh + GROUP * 64 + GROUP * Kw + GROUP * Kw + GROUP)
__global__ __launch_bounds__(384) void finalize(
    const int* __restrict__ vlen,
    const float* __restrict__ sw, const float* __restrict__ sb,
    const float* __restrict__ rsw, const float* __restrict__ rsb,
    const float* __restrict__ cw, const float* __restrict__ cb,
    const float* __restrict__ ow, const float* __restrict__ ob,
    float* __restrict__ out) {
    extern __shared__ float sm[];
    float* lh   = sm;
    float* th   = lh + GROUP * 3840;
    float* rn   = th + GROUP * Hh;
    float* s1   = rn + GROUP * Hh;
    float* ldw  = s1 + GROUP * 64;
    float* dtmp = ldw + GROUP * Kw;
    int*   tbs  = (int*)(dtmp + GROUP * Kw);

    const int tid = threadIdx.x;
    const int b0 = blockIdx.x * GROUP;

    if (tid < GROUP) tbs[tid] = vlen[b0 + tid] - 1;
    __syncthreads();
    if (tid < GROUP * Kw) {
        int g = tid / Kw, j = tid % Kw;
        int ts = tbs[g] - (Kw - 1) + j;
        dtmp[g * Kw + j] = (ts >= 0) ? g_dist[ts * Bsz + b0 + g] : 0.0f;
    }
    __syncthreads();
    if (tid < GROUP) {
        float c = 0.0f, cums[Kw];
#pragma unroll
        for (int j = 0; j < Kw; j++) { c += dtmp[tid * Kw + j]; cums[j] = c; }
        float m = cums[Kw - 1];
        float s = 0.0f, e[Kw];
#pragma unroll
        for (int j = 0; j < Kw; j++) { e[j] = __expf(cums[j] - m); s += e[j]; }
        float inv = 1.0f / s;
#pragma unroll
        for (int j = 0; j < Kw; j++) ldw[tid * Kw + j] = e[j] * inv;
    }
    __syncthreads();

    for (int g = 0; g < GROUP; g++) {
        int tb = tbs[g], b = b0 + g;
        float tr = 0.0f;
#pragma unroll
        for (int j = 0; j < Kw; j++) {
            int ts = tb - (Kw - 1) + j;
            float hv = (ts >= 0) ? g_hhistT[((size_t)ts * Hh + tid) * Bsz + b] : 0.0f;
            float v = hv * ldw[g * Kw + j];
            lh[g * 3840 + j * Hh + tid] = v;
            tr += v;
        }
        th[g * Hh + tid] = tr * 0.1f;
    }
    __syncthreads();

    if (tid < GROUP * 64) {
        int g = tid >> 6, j = tid & 63;
        float a = sb[j];
        for (int h = 0; h < Hh; h++) a += th[g * Hh + h] * sw[h * 64 + j];
        s1[g * 64 + j] = fmaxf(a, 0.0f);
    }
    __syncthreads();

    float accv[GROUP];
    float cbv = cb[tid];
#pragma unroll
    for (int g = 0; g < GROUP; g++) accv[g] = cbv;
    const float2* cwp = (const float2*)(cw + (size_t)tid * (Hh * Kw));
    for (int h = 0; h < Hh; h++) {
#pragma unroll
        for (int jp = 0; jp < Kw / 2; jp++) {
            float2 w = cwp[h * (Kw / 2) + jp];
            int j0 = jp * 2;
#pragma unroll
            for (int g = 0; g < GROUP; g++) {
                accv[g] += lh[g * 3840 + j0 * Hh + h] * w.x
                         + lh[g * 3840 + (j0 + 1) * Hh + h] * w.y;
            }
        }
    }

    for (int g = 0; g < GROUP; g++) {
        float a = rsb[tid];
#pragma unroll
        for (int j = 0; j < 64; j++) a += s1[g * 64 + j] * rsw[j * Hh + tid];
        float t2 = sigf(a);
        int tb = tbs[g], b = b0 + g;
        float hf = g_hhistT[((size_t)tb * Hh + tid) * Bsz + b];
        rn[g * Hh + tid] = hf + t2 * accv[g];
    }
    __syncthreads();

    if (tid < GROUP * LAB) {
        int g = tid / LAB, lab = tid % LAB;
        float a = ob[lab];
        for (int h = 0; h < Hh; h++) a += rn[g * Hh + h] * ow[h * LAB + lab];
        out[(b0 + g) * LAB + lab] = a;
    }
}

// ---------------- launch ----------------
#define REC_SMEM ((384*52 + 2*48*128 + 48*128 + 12*130*6 + 128*6 + 12*6) * (int)sizeof(float))

extern "C" void kernel_launch(void* const* d_in, const int* in_sizes, int n_in,
                              void* d_out, int out_size) {
    const float* X   = (const float*)d_in[0];
    const int*   vlen= (const int*)  d_in[1];
    const float* kw  = (const float*)d_in[2];
    const float* kb  = (const float*)d_in[3];
    const float* rw  = (const float*)d_in[4];
    const float* rb  = (const float*)d_in[5];
    const float* sw  = (const float*)d_in[6];
    const float* sb  = (const float*)d_in[7];
    const float* rsw = (const float*)d_in[8];
    const float* rsb = (const float*)d_in[9];
    const float* cw  = (const float*)d_in[10];
    const float* cb  = (const float*)d_in[11];
    const float* ow  = (const float*)d_in[12];
    const float* ob  = (const float*)d_in[13];
    float* out = (float*)d_out;

    cudaFuncSetAttribute(finalize, cudaFuncAttributeMaxDynamicSharedMemorySize,
                         FIN_SMEM_FLOATS * (int)sizeof(float));
    cudaFuncSetAttribute(recurrence, cudaFuncAttributeMaxDynamicSharedMemorySize,
                         REC_SMEM);

    init_state<<<148, 512>>>();
    prep_B<<<(NHT * Hh * NTW + 255) / 256, 256>>>(rw);
    gemm_xw<<<dim3((GATES + 127) / 128, (Bsz * Tt) / 128), 256>>>(X, kw, kb, rw, rb);
    transpose_xw<<<dim3((GATES + 31) / 32, Bsz / 32, Tt), 256>>>();
    recurrence<<<NCTA, 384, REC_SMEM>>>(rw);
    finalize<<<Bsz / GROUP, Hh, FIN_SMEM_FLOATS * (int)sizeof(float)>>>(
        vlen, sw, sb, rsw, rsb, cw, cb, ow, ob, out);
}